// round 5
// baseline (speedup 1.0000x reference)
#include <cuda_runtime.h>
#include <cuda_bf16.h>

#define N_NODES 8192
#define FIN 128
#define FOUT 64
#define EMAX 262144

// Scratch (allocation-free rule: __device__ globals)
__device__ int   g_cnt[N_NODES];          // zero at entry; k_scan re-zeros after reading
__device__ int   g_off[N_NODES + 1];
__device__ int   g_cur[N_NODES];
__device__ int   g_srcs[EMAX];
__device__ float g_dinv[N_NODES];
__device__ float g_h[N_NODES * FOUT];
__device__ float g_z[N_NODES * FOUT];

// ---------------------------------------------------------------- count in-degree per dst
__global__ void k_count(const int* __restrict__ ei, int E) {
    int e = blockIdx.x * blockDim.x + threadIdx.x;
    if (e < E) atomicAdd(&g_cnt[ei[E + e]], 1);
}

// ---------------------------------------------------------------- exclusive scan (1 block) + reset cnt
__global__ void k_scan() {
    __shared__ int sA[1024], sB[1024];
    int t = threadIdx.x;
    int base = t * 8;
    int v[8];
    int sum = 0;
#pragma unroll
    for (int i = 0; i < 8; i++) { v[i] = g_cnt[base + i]; sum += v[i]; }
#pragma unroll
    for (int i = 0; i < 8; i++) g_cnt[base + i] = 0;   // leave zeroed for next run
    sA[t] = sum;
    __syncthreads();
    int* src = sA; int* dst = sB;
    for (int off = 1; off < 1024; off <<= 1) {
        int val = src[t];
        if (t >= off) val += src[t - off];
        dst[t] = val;
        __syncthreads();
        int* tmp = src; src = dst; dst = tmp;
    }
    int excl = src[t] - sum;
    int run = excl;
#pragma unroll
    for (int i = 0; i < 8; i++) {
        g_off[base + i] = run;
        run += v[i];
        g_cur[base + i] = 0;
        g_dinv[base + i] = rsqrtf((float)(v[i] + 1));   // +1 self loop
    }
    if (t == 1023) g_off[N_NODES] = run;                // total = E
}

// ---------------------------------------------------------------- scatter srcs into CSR
__global__ void k_scatter(const int* __restrict__ ei, int E) {
    int e = blockIdx.x * blockDim.x + threadIdx.x;
    if (e < E) {
        int s = ei[e];
        int d = ei[E + e];
        int pos = g_off[d] + atomicAdd(&g_cur[d], 1);
        g_srcs[pos] = s;
    }
}

// ---------------------------------------------------------------- h = x^T @ W : smem-W tiled
// block: 256 threads -> 128 rows x 2 halves; warps 0-3 half 0, warps 4-7 half 1
__global__ void __launch_bounds__(256) k_h(const float* __restrict__ x,
                                           const float* __restrict__ W) {
    __shared__ float sW[FIN * FOUT];   // 32 KB
    int tid = threadIdx.x;
#pragma unroll
    for (int i = 0; i < 8; i++)
        ((float4*)sW)[tid + i * 256] = ((const float4*)W)[tid + i * 256];
    __syncthreads();

    int row = blockIdx.x * 128 + (tid & 127);
    int half = tid >> 7;                       // 0 or 1 -> output cols [half*32, +32)
    const float4* sW4 = (const float4*)sW;

    unsigned long long acc2[16];
#pragma unroll
    for (int i = 0; i < 16; i++) acc2[i] = 0ull;

#pragma unroll 4
    for (int k = 0; k < FIN; k++) {
        float xv = __ldg(&x[k * N_NODES + row]);        // coalesced 128B per warp
        unsigned long long a2;
        asm("mov.b64 %0, {%1, %1};" : "=l"(a2) : "f"(xv));
        const float4* wrow = &sW4[k * 16 + half * 8];   // 32 floats
#pragma unroll
        for (int q = 0; q < 8; q++) {
            float4 w = wrow[q];                         // LDS.128 broadcast
            unsigned long long w0, w1;
            asm("mov.b64 %0, {%1, %2};" : "=l"(w0) : "f"(w.x), "f"(w.y));
            asm("mov.b64 %0, {%1, %2};" : "=l"(w1) : "f"(w.z), "f"(w.w));
            asm("fma.rn.f32x2 %0, %1, %2, %0;" : "+l"(acc2[q * 2])     : "l"(a2), "l"(w0));
            asm("fma.rn.f32x2 %0, %1, %2, %0;" : "+l"(acc2[q * 2 + 1]) : "l"(a2), "l"(w1));
        }
    }
    // write 32 contiguous floats
    float* hp = &g_h[row * FOUT + half * 32];
#pragma unroll
    for (int q = 0; q < 8; q++) {
        float x0, y0, x1, y1;
        asm("mov.b64 {%0, %1}, %2;" : "=f"(x0), "=f"(y0) : "l"(acc2[q * 2]));
        asm("mov.b64 {%0, %1}, %2;" : "=f"(x1), "=f"(y1) : "l"(acc2[q * 2 + 1]));
        ((float4*)hp)[q] = make_float4(x0, y0, x1, y1);
    }
}

// ---------------------------------------------------------------- atomic-free gather: warp per dst
__global__ void k_gather(const float* __restrict__ b) {
    int warp = (blockIdx.x * blockDim.x + threadIdx.x) >> 5;
    int lane = threadIdx.x & 31;
    if (warp >= N_NODES) return;
    int d = warp;
    float dd = g_dinv[d];
    int beg = g_off[d];
    int cnt = g_off[d + 1] - beg;
    float a0 = dd * g_h[d * FOUT + lane];                    // self loop
    float a1 = dd * g_h[d * FOUT + lane + 32];
    int j = 0;
    for (; j + 2 <= cnt; j += 2) {
        int s0 = __ldg(&g_srcs[beg + j]);
        int s1 = __ldg(&g_srcs[beg + j + 1]);
        float ds0 = __ldg(&g_dinv[s0]);
        float ds1 = __ldg(&g_dinv[s1]);
        a0 = fmaf(ds0, __ldg(&g_h[s0 * FOUT + lane]), a0);
        a1 = fmaf(ds0, __ldg(&g_h[s0 * FOUT + lane + 32]), a1);
        a0 = fmaf(ds1, __ldg(&g_h[s1 * FOUT + lane]), a0);
        a1 = fmaf(ds1, __ldg(&g_h[s1 * FOUT + lane + 32]), a1);
    }
    if (j < cnt) {
        int s0 = __ldg(&g_srcs[beg + j]);
        float ds0 = __ldg(&g_dinv[s0]);
        a0 = fmaf(ds0, __ldg(&g_h[s0 * FOUT + lane]), a0);
        a1 = fmaf(ds0, __ldg(&g_h[s0 * FOUT + lane + 32]), a1);
    }
    g_z[d * FOUT + lane]      = fmaf(dd, a0, b[lane]);
    g_z[d * FOUT + lane + 32] = fmaf(dd, a1, b[lane + 32]);
}

// ---------------------------------------------------------------- sigmoid(z z^T), symmetric tiling
__device__ __forceinline__ float sigmoid_tanh(float v) {
    float t;
    asm("tanh.approx.f32 %0, %1;" : "=f"(t) : "f"(0.5f * v));
    return fmaf(0.5f, t, 0.5f);
}

__global__ void __launch_bounds__(256, 2) k_gemm_sym(float* __restrict__ out) {
    const int bi = blockIdx.y, bj = blockIdx.x;
    if (bj < bi) return;
    const int i0 = bi * 128, j0 = bj * 128;

    __shared__ float As[32][132];   // [k][row]; stride 132: 16B-aligned rows for LDS.128
    __shared__ float Bs[32][132];

    const int tid = threadIdx.x;
    const int tx = tid & 15;
    const int ty = tid >> 4;

    unsigned long long acc2[8][4];
#pragma unroll
    for (int r = 0; r < 8; r++)
#pragma unroll
        for (int cp = 0; cp < 4; cp++) acc2[r][cp] = 0ull;

    for (int kc = 0; kc < FOUT; kc += 32) {
#pragma unroll
        for (int it = 0; it < 4; it++) {
            int idx = tid + it * 256;
            int row = idx >> 3;
            int c4 = idx & 7;
            float4 v = *(const float4*)&g_z[(i0 + row) * FOUT + kc + c4 * 4];
            As[c4 * 4 + 0][row] = v.x;
            As[c4 * 4 + 1][row] = v.y;
            As[c4 * 4 + 2][row] = v.z;
            As[c4 * 4 + 3][row] = v.w;
            float4 u = *(const float4*)&g_z[(j0 + row) * FOUT + kc + c4 * 4];
            Bs[c4 * 4 + 0][row] = u.x;
            Bs[c4 * 4 + 1][row] = u.y;
            Bs[c4 * 4 + 2][row] = u.z;
            Bs[c4 * 4 + 3][row] = u.w;
        }
        __syncthreads();

#pragma unroll
        for (int k = 0; k < 32; k++) {
            float4 aL = *(const float4*)&As[k][ty * 8];
            float4 aH = *(const float4*)&As[k][ty * 8 + 4];
            ulonglong2 bL = *(const ulonglong2*)&Bs[k][tx * 8];
            ulonglong2 bH = *(const ulonglong2*)&Bs[k][tx * 8 + 4];
            unsigned long long b2[4] = { bL.x, bL.y, bH.x, bH.y };
            float a[8] = { aL.x, aL.y, aL.z, aL.w, aH.x, aH.y, aH.z, aH.w };
#pragma unroll
            for (int r = 0; r < 8; r++) {
                unsigned long long a2;
                asm("mov.b64 %0, {%1, %1};" : "=l"(a2) : "f"(a[r]));
#pragma unroll
                for (int cp = 0; cp < 4; cp++) {
                    asm("fma.rn.f32x2 %0, %1, %2, %0;"
                        : "+l"(acc2[r][cp]) : "l"(a2), "l"(b2[cp]));
                }
            }
        }
        __syncthreads();
    }

    float s[8][8];
#pragma unroll
    for (int r = 0; r < 8; r++)
#pragma unroll
        for (int cp = 0; cp < 4; cp++) {
            float lo, hi;
            asm("mov.b64 {%0, %1}, %2;" : "=f"(lo), "=f"(hi) : "l"(acc2[r][cp]));
            s[r][cp * 2 + 0] = sigmoid_tanh(lo);
            s[r][cp * 2 + 1] = sigmoid_tanh(hi);
        }

#pragma unroll
    for (int r = 0; r < 8; r++) {
        int row = i0 + ty * 8 + r;
        float4* p = (float4*)&out[row * N_NODES + j0 + tx * 8];
        p[0] = make_float4(s[r][0], s[r][1], s[r][2], s[r][3]);
        p[1] = make_float4(s[r][4], s[r][5], s[r][6], s[r][7]);
    }
    if (bi != bj) {
#pragma unroll
        for (int c = 0; c < 8; c++) {
            int row = j0 + tx * 8 + c;
            float4* p = (float4*)&out[row * N_NODES + i0 + ty * 8];
            p[0] = make_float4(s[0][c], s[1][c], s[2][c], s[3][c]);
            p[1] = make_float4(s[4][c], s[5][c], s[6][c], s[7][c]);
        }
    }
}

// ----------------------------------------------------------------
extern "C" void kernel_launch(void* const* d_in, const int* in_sizes, int n_in,
                              void* d_out, int out_size) {
    const float* x  = (const float*)d_in[0];       // [128, 8192]
    const int*   ei = (const int*)d_in[1];         // [2, E] int32
    const float* W  = (const float*)d_in[2];       // [128, 64]
    const float* b  = (const float*)d_in[3];       // [64]
    float* out = (float*)d_out;                    // [8192, 8192]
    const int E = in_sizes[1] / 2;

    k_count<<<(E + 255) / 256, 256>>>(ei, E);          // 1
    k_scan<<<1, 1024>>>();                             // 2
    k_h<<<N_NODES / 128, 256>>>(x, W);                 // 3
    k_scatter<<<(E + 255) / 256, 256>>>(ei, E);        // 4
    k_gather<<<(N_NODES * 32) / 256, 256>>>(b);        // 5
    dim3 grid(N_NODES / 128, N_NODES / 128);
    k_gemm_sym<<<grid, 256>>>(out);                    // 6  <- ncu -s 5 captures this
}

// round 6
// speedup vs baseline: 1.0985x; 1.0985x over previous
#include <cuda_runtime.h>
#include <cuda_bf16.h>

#define N_NODES 8192
#define FIN 128
#define FOUT 64
#define EMAX 262144

// Scratch (allocation-free rule: __device__ globals)
__device__ int   g_cnt[N_NODES];          // zero at entry; gemm dead-blocks re-zero it
__device__ float g_h[N_NODES * FOUT];
__device__ float g_z[N_NODES * FOUT];

// ---------------------------------------------------------------- launch 1: fused edge-count + h GEMM
// blocks [0,1024): degree count.  blocks [1024,1088): h = x^T @ W (smem-W tiled)
__global__ void __launch_bounds__(256) k_count_h(const int* __restrict__ ei, int E,
                                                 const float* __restrict__ x,
                                                 const float* __restrict__ W) {
    int tid = threadIdx.x;
    if (blockIdx.x < 1024) {
        int e = blockIdx.x * 256 + tid;
        if (e < E) atomicAdd(&g_cnt[ei[E + e]], 1);
        return;
    }
    // ---- h part ----
    __shared__ float sW[FIN * FOUT];   // 32 KB
#pragma unroll
    for (int i = 0; i < 8; i++)
        ((float4*)sW)[tid + i * 256] = ((const float4*)W)[tid + i * 256];
    __syncthreads();

    int row = (blockIdx.x - 1024) * 128 + (tid & 127);
    int half = tid >> 7;
    const float4* sW4 = (const float4*)sW;

    unsigned long long acc2[16];
#pragma unroll
    for (int i = 0; i < 16; i++) acc2[i] = 0ull;

#pragma unroll 4
    for (int k = 0; k < FIN; k++) {
        float xv = __ldg(&x[k * N_NODES + row]);
        unsigned long long a2;
        asm("mov.b64 %0, {%1, %1};" : "=l"(a2) : "f"(xv));
        const float4* wrow = &sW4[k * 16 + half * 8];
#pragma unroll
        for (int q = 0; q < 8; q++) {
            float4 w = wrow[q];
            unsigned long long w0, w1;
            asm("mov.b64 %0, {%1, %2};" : "=l"(w0) : "f"(w.x), "f"(w.y));
            asm("mov.b64 %0, {%1, %2};" : "=l"(w1) : "f"(w.z), "f"(w.w));
            asm("fma.rn.f32x2 %0, %1, %2, %0;" : "+l"(acc2[q * 2])     : "l"(a2), "l"(w0));
            asm("fma.rn.f32x2 %0, %1, %2, %0;" : "+l"(acc2[q * 2 + 1]) : "l"(a2), "l"(w1));
        }
    }
    float* hp = &g_h[row * FOUT + half * 32];
#pragma unroll
    for (int q = 0; q < 8; q++) {
        float x0, y0, x1, y1;
        asm("mov.b64 {%0, %1}, %2;" : "=f"(x0), "=f"(y0) : "l"(acc2[q * 2]));
        asm("mov.b64 {%0, %1}, %2;" : "=f"(x1), "=f"(y1) : "l"(acc2[q * 2 + 1]));
        ((float4*)hp)[q] = make_float4(x0, y0, x1, y1);
    }
}

// ---------------------------------------------------------------- launch 2: z = h/deg + b (self loop)
__global__ void k_zinit(const float* __restrict__ b) {
    int gid = blockIdx.x * blockDim.x + threadIdx.x;   // N * 16
    int n = gid >> 4, q = gid & 15;
    float inv = 1.0f / (float)(g_cnt[n] + 1);
    float4 h = *(const float4*)&g_h[n * FOUT + q * 4];
    float4 bb = __ldg(&((const float4*)b)[q]);
    float4 z;
    z.x = fmaf(h.x, inv, bb.x);
    z.y = fmaf(h.y, inv, bb.y);
    z.z = fmaf(h.z, inv, bb.z);
    z.w = fmaf(h.w, inv, bb.w);
    *(float4*)&g_z[n * FOUT + q * 4] = z;
}

// ---------------------------------------------------------------- launch 3: edge scatter, vector red
__global__ void k_edges(const int* __restrict__ ei, int E) {
    int gid = blockIdx.x * blockDim.x + threadIdx.x;   // E * 16
    int e = gid >> 4, q = gid & 15;
    if (e >= E) return;
    int s = __ldg(&ei[e]);
    int d = __ldg(&ei[E + e]);
    float degp = (float)((g_cnt[s] + 1) * (g_cnt[d] + 1));
    float c = rsqrtf(degp);                            // dinv[s]*dinv[d]
    float4 h = *(const float4*)&g_h[s * FOUT + q * 4];
    float* zp = &g_z[d * FOUT + q * 4];
    asm volatile("red.global.add.v4.f32 [%0], {%1, %2, %3, %4};"
                 :: "l"(zp), "f"(h.x * c), "f"(h.y * c), "f"(h.z * c), "f"(h.w * c)
                 : "memory");
}

// ---------------------------------------------------------------- launch 4: sigmoid(z z^T), symmetric
__device__ __forceinline__ float sigmoid_tanh(float v) {
    float t;
    asm("tanh.approx.f32 %0, %1;" : "=f"(t) : "f"(0.5f * v));
    return fmaf(0.5f, t, 0.5f);
}

__global__ void __launch_bounds__(256, 2) k_gemm_sym(float* __restrict__ out) {
    const int bi = blockIdx.y, bj = blockIdx.x;
    if (bj < bi) {
        // dead blocks: re-zero g_cnt for the next graph replay (cnt unused after launch 3)
        if (bj == 0 && bi >= 1 && bi <= 32) {
            g_cnt[(bi - 1) * 256 + threadIdx.x] = 0;
        }
        return;
    }
    const int i0 = bi * 128, j0 = bj * 128;

    __shared__ float As[32][132];   // [k][row]; 16B-aligned rows for LDS.128
    __shared__ float Bs[32][132];

    const int tid = threadIdx.x;
    const int tx = tid & 15;
    const int ty = tid >> 4;

    unsigned long long acc2[8][4];
#pragma unroll
    for (int r = 0; r < 8; r++)
#pragma unroll
        for (int cp = 0; cp < 4; cp++) acc2[r][cp] = 0ull;

    for (int kc = 0; kc < FOUT; kc += 32) {
#pragma unroll
        for (int it = 0; it < 4; it++) {
            int idx = tid + it * 256;
            int row = idx >> 3;
            int c4 = idx & 7;
            float4 v = *(const float4*)&g_z[(i0 + row) * FOUT + kc + c4 * 4];
            As[c4 * 4 + 0][row] = v.x;
            As[c4 * 4 + 1][row] = v.y;
            As[c4 * 4 + 2][row] = v.z;
            As[c4 * 4 + 3][row] = v.w;
            float4 u = *(const float4*)&g_z[(j0 + row) * FOUT + kc + c4 * 4];
            Bs[c4 * 4 + 0][row] = u.x;
            Bs[c4 * 4 + 1][row] = u.y;
            Bs[c4 * 4 + 2][row] = u.z;
            Bs[c4 * 4 + 3][row] = u.w;
        }
        __syncthreads();

#pragma unroll
        for (int k = 0; k < 32; k++) {
            ulonglong2 bL = *(const ulonglong2*)&Bs[k][tx * 8];
            ulonglong2 bH = *(const ulonglong2*)&Bs[k][tx * 8 + 4];
            unsigned long long b2[4] = { bL.x, bL.y, bH.x, bH.y };
            // first 4 rows
            float4 aL = *(const float4*)&As[k][ty * 8];
            float aLv[4] = { aL.x, aL.y, aL.z, aL.w };
#pragma unroll
            for (int r = 0; r < 4; r++) {
                unsigned long long a2;
                asm("mov.b64 %0, {%1, %1};" : "=l"(a2) : "f"(aLv[r]));
#pragma unroll
                for (int cp = 0; cp < 4; cp++)
                    asm("fma.rn.f32x2 %0, %1, %2, %0;"
                        : "+l"(acc2[r][cp]) : "l"(a2), "l"(b2[cp]));
            }
            // second 4 rows
            float4 aH = *(const float4*)&As[k][ty * 8 + 4];
            float aHv[4] = { aH.x, aH.y, aH.z, aH.w };
#pragma unroll
            for (int r = 0; r < 4; r++) {
                unsigned long long a2;
                asm("mov.b64 %0, {%1, %1};" : "=l"(a2) : "f"(aHv[r]));
#pragma unroll
                for (int cp = 0; cp < 4; cp++)
                    asm("fma.rn.f32x2 %0, %1, %2, %0;"
                        : "+l"(acc2[r + 4][cp]) : "l"(a2), "l"(b2[cp]));
            }
        }
        __syncthreads();
    }

    float s[8][8];
#pragma unroll
    for (int r = 0; r < 8; r++)
#pragma unroll
        for (int cp = 0; cp < 4; cp++) {
            float lo, hi;
            asm("mov.b64 {%0, %1}, %2;" : "=f"(lo), "=f"(hi) : "l"(acc2[r][cp]));
            s[r][cp * 2 + 0] = sigmoid_tanh(lo);
            s[r][cp * 2 + 1] = sigmoid_tanh(hi);
        }

#pragma unroll
    for (int r = 0; r < 8; r++) {
        int row = i0 + ty * 8 + r;
        float4* p = (float4*)&out[row * N_NODES + j0 + tx * 8];
        p[0] = make_float4(s[r][0], s[r][1], s[r][2], s[r][3]);
        p[1] = make_float4(s[r][4], s[r][5], s[r][6], s[r][7]);
    }
    if (bi != bj) {
#pragma unroll
        for (int c = 0; c < 8; c++) {
            int row = j0 + tx * 8 + c;
            float4* p = (float4*)&out[row * N_NODES + i0 + ty * 8];
            p[0] = make_float4(s[0][c], s[1][c], s[2][c], s[3][c]);
            p[1] = make_float4(s[4][c], s[5][c], s[6][c], s[7][c]);
        }
    }
}

// ----------------------------------------------------------------
extern "C" void kernel_launch(void* const* d_in, const int* in_sizes, int n_in,
                              void* d_out, int out_size) {
    const float* x  = (const float*)d_in[0];       // [128, 8192]
    const int*   ei = (const int*)d_in[1];         // [2, E] int32
    const float* W  = (const float*)d_in[2];       // [128, 64]
    const float* b  = (const float*)d_in[3];       // [64]
    float* out = (float*)d_out;                    // [8192, 8192]
    const int E = in_sizes[1] / 2;

    k_count_h<<<1024 + N_NODES / 128, 256>>>(ei, E, x, W);   // 1
    k_zinit<<<(N_NODES * 16) / 256, 256>>>(b);               // 2
    k_edges<<<(E * 16) / 256, 256>>>(ei, E);                 // 3
    dim3 grid(N_NODES / 128, N_NODES / 128);
    k_gemm_sym<<<grid, 256>>>(out);                          // 4 <- ncu captures this
}

// round 8
// speedup vs baseline: 1.2379x; 1.1269x over previous
#include <cuda_runtime.h>
#include <cuda_bf16.h>

#define N_NODES 8192
#define FIN 128
#define FOUT 64
#define EMAX 262144

// Scratch (allocation-free rule: __device__ globals)
__device__ int   g_cnt[N_NODES];          // zero at entry; gemm dead-blocks re-zero it
__device__ float g_h[N_NODES * FOUT];
__device__ float g_z[N_NODES * FOUT];

// ---------------------------------------------------------------- launch 1: fused edge-count + h GEMM
__global__ void __launch_bounds__(256) k_count_h(const int* __restrict__ ei, int E,
                                                 const float* __restrict__ x,
                                                 const float* __restrict__ W) {
    int tid = threadIdx.x;
    if (blockIdx.x < 1024) {
        int e = blockIdx.x * 256 + tid;
        if (e < E) atomicAdd(&g_cnt[ei[E + e]], 1);
        return;
    }
    __shared__ float sW[FIN * FOUT];   // 32 KB
#pragma unroll
    for (int i = 0; i < 8; i++)
        ((float4*)sW)[tid + i * 256] = ((const float4*)W)[tid + i * 256];
    __syncthreads();

    int row = (blockIdx.x - 1024) * 128 + (tid & 127);
    int half = tid >> 7;
    const float4* sW4 = (const float4*)sW;

    unsigned long long acc2[16];
#pragma unroll
    for (int i = 0; i < 16; i++) acc2[i] = 0ull;

#pragma unroll 4
    for (int k = 0; k < FIN; k++) {
        float xv = __ldg(&x[k * N_NODES + row]);
        unsigned long long a2;
        asm("mov.b64 %0, {%1, %1};" : "=l"(a2) : "f"(xv));
        const float4* wrow = &sW4[k * 16 + half * 8];
#pragma unroll
        for (int q = 0; q < 8; q++) {
            float4 w = wrow[q];
            unsigned long long w0, w1;
            asm("mov.b64 %0, {%1, %2};" : "=l"(w0) : "f"(w.x), "f"(w.y));
            asm("mov.b64 %0, {%1, %2};" : "=l"(w1) : "f"(w.z), "f"(w.w));
            asm("fma.rn.f32x2 %0, %1, %2, %0;" : "+l"(acc2[q * 2])     : "l"(a2), "l"(w0));
            asm("fma.rn.f32x2 %0, %1, %2, %0;" : "+l"(acc2[q * 2 + 1]) : "l"(a2), "l"(w1));
        }
    }
    float* hp = &g_h[row * FOUT + half * 32];
#pragma unroll
    for (int q = 0; q < 8; q++) {
        float x0, y0, x1, y1;
        asm("mov.b64 {%0, %1}, %2;" : "=f"(x0), "=f"(y0) : "l"(acc2[q * 2]));
        asm("mov.b64 {%0, %1}, %2;" : "=f"(x1), "=f"(y1) : "l"(acc2[q * 2 + 1]));
        ((float4*)hp)[q] = make_float4(x0, y0, x1, y1);
    }
}

// ---------------------------------------------------------------- launch 2: z = h/deg + b (self loop)
__global__ void k_zinit(const float* __restrict__ b) {
    int gid = blockIdx.x * blockDim.x + threadIdx.x;   // N * 16
    int n = gid >> 4, q = gid & 15;
    float inv = 1.0f / (float)(g_cnt[n] + 1);
    float4 h = *(const float4*)&g_h[n * FOUT + q * 4];
    float4 bb = __ldg(&((const float4*)b)[q]);
    float4 z;
    z.x = fmaf(h.x, inv, bb.x);
    z.y = fmaf(h.y, inv, bb.y);
    z.z = fmaf(h.z, inv, bb.z);
    z.w = fmaf(h.w, inv, bb.w);
    *(float4*)&g_z[n * FOUT + q * 4] = z;
}

// ---------------------------------------------------------------- launch 3: edge scatter, vector red
__global__ void k_edges(const int* __restrict__ ei, int E) {
    int gid = blockIdx.x * blockDim.x + threadIdx.x;   // E * 16
    int e = gid >> 4, q = gid & 15;
    if (e >= E) return;
    int s = __ldg(&ei[e]);
    int d = __ldg(&ei[E + e]);
    float degp = (float)((g_cnt[s] + 1) * (g_cnt[d] + 1));
    float c = rsqrtf(degp);                            // dinv[s]*dinv[d]
    float4 h = *(const float4*)&g_h[s * FOUT + q * 4];
    float* zp = &g_z[d * FOUT + q * 4];
    asm volatile("red.global.add.v4.f32 [%0], {%1, %2, %3, %4};"
                 :: "l"(zp), "f"(h.x * c), "f"(h.y * c), "f"(h.z * c), "f"(h.w * c)
                 : "memory");
}

// ---------------------------------------------------------------- launch 4: sigmoid(z z^T), symmetric
__device__ __forceinline__ float sigmoid_tanh(float v) {
    float t;
    asm("tanh.approx.f32 %0, %1;" : "=f"(t) : "f"(0.5f * v));
    return fmaf(0.5f, t, 0.5f);
}

__global__ void __launch_bounds__(256, 2) k_gemm_sym(float* __restrict__ out) {
    const int bi = blockIdx.y, bj = blockIdx.x;
    if (bj < bi) {
        if (bj == 0 && bi >= 1 && bi <= 32) {
            g_cnt[(bi - 1) * 256 + threadIdx.x] = 0;   // re-zero for next replay
        }
        return;
    }
    const int i0 = bi * 128, j0 = bj * 128;

    __shared__ float As[32][132];   // [k][row]; rows 16B-aligned (132*4=528=33*16)
    __shared__ float Bs[32][132];

    const int tid = threadIdx.x;
    const int tx = tid & 15;
    const int ty = tid >> 4;

    // per-thread: rows i0+ty*8..+7 ; cols j0+{4tx..4tx+3, 64+4tx..64+4tx+3}
    unsigned long long acc2[8][4];
#pragma unroll
    for (int r = 0; r < 8; r++)
#pragma unroll
        for (int cp = 0; cp < 4; cp++) acc2[r][cp] = 0ull;

    for (int kc = 0; kc < FOUT; kc += 32) {
#pragma unroll
        for (int it = 0; it < 4; it++) {
            int idx = tid + it * 256;
            int row = idx >> 3;
            int c4 = idx & 7;
            float4 v = *(const float4*)&g_z[(i0 + row) * FOUT + kc + c4 * 4];
            As[c4 * 4 + 0][row] = v.x;
            As[c4 * 4 + 1][row] = v.y;
            As[c4 * 4 + 2][row] = v.z;
            As[c4 * 4 + 3][row] = v.w;
            float4 u = *(const float4*)&g_z[(j0 + row) * FOUT + kc + c4 * 4];
            Bs[c4 * 4 + 0][row] = u.x;
            Bs[c4 * 4 + 1][row] = u.y;
            Bs[c4 * 4 + 2][row] = u.z;
            Bs[c4 * 4 + 3][row] = u.w;
        }
        __syncthreads();

#pragma unroll
        for (int k = 0; k < 32; k++) {
            // B: two conflict-free LDS.128 (16-B stride across lanes)
            float4 bb0 = *(const float4*)&Bs[k][tx * 4];        // cols 4tx..+3
            float4 bb1 = *(const float4*)&Bs[k][64 + tx * 4];   // cols 64+4tx..+3
            unsigned long long b2[4];
            asm("mov.b64 %0, {%1, %2};" : "=l"(b2[0]) : "f"(bb0.x), "f"(bb0.y));
            asm("mov.b64 %0, {%1, %2};" : "=l"(b2[1]) : "f"(bb0.z), "f"(bb0.w));
            asm("mov.b64 %0, {%1, %2};" : "=l"(b2[2]) : "f"(bb1.x), "f"(bb1.y));
            asm("mov.b64 %0, {%1, %2};" : "=l"(b2[3]) : "f"(bb1.z), "f"(bb1.w));
            // A: broadcast LDS.128 (2 distinct addrs per warp)
            float4 aL = *(const float4*)&As[k][ty * 8];
            float4 aH = *(const float4*)&As[k][ty * 8 + 4];
            float a[8] = { aL.x, aL.y, aL.z, aL.w, aH.x, aH.y, aH.z, aH.w };
#pragma unroll
            for (int r = 0; r < 8; r++) {
                unsigned long long a2;
                asm("mov.b64 %0, {%1, %1};" : "=l"(a2) : "f"(a[r]));
#pragma unroll
                for (int cp = 0; cp < 4; cp++)
                    asm("fma.rn.f32x2 %0, %1, %2, %0;"
                        : "+l"(acc2[r][cp]) : "l"(a2), "l"(b2[cp]));
            }
        }
        __syncthreads();
    }

    // epilogue: unpack + sigmoid.  s[r][0..3] -> cols j0+4tx+., s[r][4..7] -> cols j0+64+4tx+.
    float s[8][8];
#pragma unroll
    for (int r = 0; r < 8; r++)
#pragma unroll
        for (int cp = 0; cp < 4; cp++) {
            float lo, hi;
            asm("mov.b64 {%0, %1}, %2;" : "=f"(lo), "=f"(hi) : "l"(acc2[r][cp]));
            s[r][cp * 2 + 0] = sigmoid_tanh(lo);
            s[r][cp * 2 + 1] = sigmoid_tanh(hi);
        }

    // direct tile
#pragma unroll
    for (int r = 0; r < 8; r++) {
        int row = i0 + ty * 8 + r;
        *(float4*)&out[row * N_NODES + j0 + tx * 4] =
            make_float4(s[r][0], s[r][1], s[r][2], s[r][3]);
        *(float4*)&out[row * N_NODES + j0 + 64 + tx * 4] =
            make_float4(s[r][4], s[r][5], s[r][6], s[r][7]);
    }
    // mirrored tile
    if (bi != bj) {
#pragma unroll
        for (int u = 0; u < 4; u++) {
            int rowA = j0 + tx * 4 + u;
            float4* p = (float4*)&out[rowA * N_NODES + i0 + ty * 8];
            p[0] = make_float4(s[0][u], s[1][u], s[2][u], s[3][u]);
            p[1] = make_float4(s[4][u], s[5][u], s[6][u], s[7][u]);
            int rowB = j0 + 64 + tx * 4 + u;
            float4* q = (float4*)&out[rowB * N_NODES + i0 + ty * 8];
            q[0] = make_float4(s[0][4 + u], s[1][4 + u], s[2][4 + u], s[3][4 + u]);
            q[1] = make_float4(s[4][4 + u], s[5][4 + u], s[6][4 + u], s[7][4 + u]);
        }
    }
}

// ----------------------------------------------------------------
extern "C" void kernel_launch(void* const* d_in, const int* in_sizes, int n_in,
                              void* d_out, int out_size) {
    const float* x  = (const float*)d_in[0];       // [128, 8192]
    const int*   ei = (const int*)d_in[1];         // [2, E] int32
    const float* W  = (const float*)d_in[2];       // [128, 64]
    const float* b  = (const float*)d_in[3];       // [64]
    float* out = (float*)d_out;                    // [8192, 8192]
    const int E = in_sizes[1] / 2;

    k_count_h<<<1024 + N_NODES / 128, 256>>>(ei, E, x, W);   // 1
    k_zinit<<<(N_NODES * 16) / 256, 256>>>(b);               // 2
    k_edges<<<(E * 16) / 256, 256>>>(ei, E);                 // 3
    dim3 grid(N_NODES / 128, N_NODES / 128);
    k_gemm_sym<<<grid, 256>>>(out);                          // 4 <- ncu captures this
}

// round 9
// speedup vs baseline: 1.2570x; 1.0155x over previous
#include <cuda_runtime.h>
#include <cuda_bf16.h>

#define N_NODES 8192
#define FIN 128
#define FOUT 64
#define EMAX 262144

// Scratch (allocation-free rule: __device__ globals)
__device__ int   g_cnt[N_NODES];          // zero at entry; gemm dead-blocks re-zero it
__device__ float g_h[N_NODES * FOUT];
__device__ float g_z[N_NODES * FOUT];

// ---------------------------------------------------------------- launch 1: fused edge-count + h GEMM
__global__ void __launch_bounds__(256) k_count_h(const int* __restrict__ ei, int E,
                                                 const float* __restrict__ x,
                                                 const float* __restrict__ W) {
    int tid = threadIdx.x;
    if (blockIdx.x < 1024) {
        int e = blockIdx.x * 256 + tid;
        if (e < E) atomicAdd(&g_cnt[ei[E + e]], 1);
        return;
    }
    __shared__ float sW[FIN * FOUT];   // 32 KB
#pragma unroll
    for (int i = 0; i < 8; i++)
        ((float4*)sW)[tid + i * 256] = ((const float4*)W)[tid + i * 256];
    __syncthreads();

    int row = (blockIdx.x - 1024) * 128 + (tid & 127);
    int half = tid >> 7;
    const float4* sW4 = (const float4*)sW;

    unsigned long long acc2[16];
#pragma unroll
    for (int i = 0; i < 16; i++) acc2[i] = 0ull;

#pragma unroll 4
    for (int k = 0; k < FIN; k++) {
        float xv = __ldg(&x[k * N_NODES + row]);
        unsigned long long a2;
        asm("mov.b64 %0, {%1, %1};" : "=l"(a2) : "f"(xv));
        const float4* wrow = &sW4[k * 16 + half * 8];
#pragma unroll
        for (int q = 0; q < 8; q++) {
            float4 w = wrow[q];
            unsigned long long w0, w1;
            asm("mov.b64 %0, {%1, %2};" : "=l"(w0) : "f"(w.x), "f"(w.y));
            asm("mov.b64 %0, {%1, %2};" : "=l"(w1) : "f"(w.z), "f"(w.w));
            asm("fma.rn.f32x2 %0, %1, %2, %0;" : "+l"(acc2[q * 2])     : "l"(a2), "l"(w0));
            asm("fma.rn.f32x2 %0, %1, %2, %0;" : "+l"(acc2[q * 2 + 1]) : "l"(a2), "l"(w1));
        }
    }
    float* hp = &g_h[row * FOUT + half * 32];
#pragma unroll
    for (int q = 0; q < 8; q++) {
        float x0, y0, x1, y1;
        asm("mov.b64 {%0, %1}, %2;" : "=f"(x0), "=f"(y0) : "l"(acc2[q * 2]));
        asm("mov.b64 {%0, %1}, %2;" : "=f"(x1), "=f"(y1) : "l"(acc2[q * 2 + 1]));
        ((float4*)hp)[q] = make_float4(x0, y0, x1, y1);
    }
}

// ---------------------------------------------------------------- launch 2: z = h/deg + b (self loop)
__global__ void k_zinit(const float* __restrict__ b) {
    int gid = blockIdx.x * blockDim.x + threadIdx.x;   // N * 16
    int n = gid >> 4, q = gid & 15;
    float inv = 1.0f / (float)(g_cnt[n] + 1);
    float4 h = *(const float4*)&g_h[n * FOUT + q * 4];
    float4 bb = __ldg(&((const float4*)b)[q]);
    float4 z;
    z.x = fmaf(h.x, inv, bb.x);
    z.y = fmaf(h.y, inv, bb.y);
    z.z = fmaf(h.z, inv, bb.z);
    z.w = fmaf(h.w, inv, bb.w);
    *(float4*)&g_z[n * FOUT + q * 4] = z;
}

// ---------------------------------------------------------------- launch 3: edge scatter, vector red
__global__ void k_edges(const int* __restrict__ ei, int E) {
    int gid = blockIdx.x * blockDim.x + threadIdx.x;   // E * 16
    int e = gid >> 4, q = gid & 15;
    if (e >= E) return;
    int s = __ldg(&ei[e]);
    int d = __ldg(&ei[E + e]);
    float degp = (float)((g_cnt[s] + 1) * (g_cnt[d] + 1));
    float c = rsqrtf(degp);                            // dinv[s]*dinv[d]
    float4 h = *(const float4*)&g_h[s * FOUT + q * 4];
    float* zp = &g_z[d * FOUT + q * 4];
    asm volatile("red.global.add.v4.f32 [%0], {%1, %2, %3, %4};"
                 :: "l"(zp), "f"(h.x * c), "f"(h.y * c), "f"(h.z * c), "f"(h.w * c)
                 : "memory");
}

// ---------------------------------------------------------------- launch 4: sigmoid(z z^T), symmetric
__device__ __forceinline__ float sigmoid_tanh(float v) {
    float t;
    asm("tanh.approx.f32 %0, %1;" : "=f"(t) : "f"(0.5f * v));
    return fmaf(0.5f, t, 0.5f);
}

__global__ void __launch_bounds__(256, 2) k_gemm_sym(float* __restrict__ out) {
    const int bi = blockIdx.y, bj = blockIdx.x;
    if (bj < bi) {
        if (bj == 0 && bi >= 1 && bi <= 32) {
            g_cnt[(bi - 1) * 256 + threadIdx.x] = 0;   // re-zero for next replay
        }
        return;
    }
    const int i0 = bi * 128, j0 = bj * 128;

    __shared__ float As[32][132];   // [k][row]; rows 16B-aligned (132*4 = 33*16)
    __shared__ float Bs[32][132];

    const int tid  = threadIdx.x;
    const int warp = tid >> 5;
    const int lane = tid & 31;
    const int wr = warp >> 1;      // warp row-block 0-3  (32 rows each)
    const int wc = warp & 1;       // warp col-block 0-1  (64 cols each)
    const int lr = lane & 3;       // lane row-group 0-3  (8 rows each)
    const int lc = lane >> 2;      // lane col-group 0-7  (4+4 cols, split)

    const int rbase = wr * 32 + lr * 8;        // 8 rows: rbase..rbase+7
    const int cbase = wc * 64 + lc * 4;        // cols cbase..+3 and cbase+32..+35

    unsigned long long acc2[8][4];
#pragma unroll
    for (int r = 0; r < 8; r++)
#pragma unroll
        for (int cp = 0; cp < 4; cp++) acc2[r][cp] = 0ull;

    for (int kc = 0; kc < FOUT; kc += 32) {
#pragma unroll
        for (int it = 0; it < 4; it++) {
            int idx = tid + it * 256;
            int row = idx >> 3;
            int c4 = idx & 7;
            float4 v = *(const float4*)&g_z[(i0 + row) * FOUT + kc + c4 * 4];
            As[c4 * 4 + 0][row] = v.x;
            As[c4 * 4 + 1][row] = v.y;
            As[c4 * 4 + 2][row] = v.z;
            As[c4 * 4 + 3][row] = v.w;
            float4 u = *(const float4*)&g_z[(j0 + row) * FOUT + kc + c4 * 4];
            Bs[c4 * 4 + 0][row] = u.x;
            Bs[c4 * 4 + 1][row] = u.y;
            Bs[c4 * 4 + 2][row] = u.z;
            Bs[c4 * 4 + 3][row] = u.w;
        }
        __syncthreads();

#pragma unroll
        for (int k = 0; k < 32; k++) {
            // B: 2 LDS.128, 8 lanes x 16B contiguous 128B -> 1 wavefront each
            ulonglong2 b0 = *(const ulonglong2*)&Bs[k][cbase];
            ulonglong2 b1 = *(const ulonglong2*)&Bs[k][cbase + 32];
            unsigned long long b2[4] = { b0.x, b0.y, b1.x, b1.y };
            // A: 2 LDS.128, 4 distinct 16B in one 128B line -> 1 wavefront each
            float4 aL = *(const float4*)&As[k][rbase];
            float4 aH = *(const float4*)&As[k][rbase + 4];
            float a[8] = { aL.x, aL.y, aL.z, aL.w, aH.x, aH.y, aH.z, aH.w };
#pragma unroll
            for (int r = 0; r < 8; r++) {
                unsigned long long a2;
                asm("mov.b64 %0, {%1, %1};" : "=l"(a2) : "f"(a[r]));
#pragma unroll
                for (int cp = 0; cp < 4; cp++)
                    asm("fma.rn.f32x2 %0, %1, %2, %0;"
                        : "+l"(acc2[r][cp]) : "l"(a2), "l"(b2[cp]));
            }
        }
        __syncthreads();
    }

    // epilogue: unpack + sigmoid.  s[r][0..3] -> cols cbase+., s[r][4..7] -> cols cbase+32+.
    float s[8][8];
#pragma unroll
    for (int r = 0; r < 8; r++)
#pragma unroll
        for (int cp = 0; cp < 4; cp++) {
            float lo, hi;
            asm("mov.b64 {%0, %1}, %2;" : "=f"(lo), "=f"(hi) : "l"(acc2[r][cp]));
            s[r][cp * 2 + 0] = sigmoid_tanh(lo);
            s[r][cp * 2 + 1] = sigmoid_tanh(hi);
        }

    // direct tile
#pragma unroll
    for (int r = 0; r < 8; r++) {
        int row = i0 + rbase + r;
        *(float4*)&out[row * N_NODES + j0 + cbase] =
            make_float4(s[r][0], s[r][1], s[r][2], s[r][3]);
        *(float4*)&out[row * N_NODES + j0 + cbase + 32] =
            make_float4(s[r][4], s[r][5], s[r][6], s[r][7]);
    }
    // mirrored tile
    if (bi != bj) {
#pragma unroll
        for (int u = 0; u < 4; u++) {
            int rowA = j0 + cbase + u;
            float4* p = (float4*)&out[rowA * N_NODES + i0 + rbase];
            p[0] = make_float4(s[0][u], s[1][u], s[2][u], s[3][u]);
            p[1] = make_float4(s[4][u], s[5][u], s[6][u], s[7][u]);
            int rowB = j0 + cbase + 32 + u;
            float4* q = (float4*)&out[rowB * N_NODES + i0 + rbase];
            q[0] = make_float4(s[0][4 + u], s[1][4 + u], s[2][4 + u], s[3][4 + u]);
            q[1] = make_float4(s[4][4 + u], s[5][4 + u], s[6][4 + u], s[7][4 + u]);
        }
    }
}

// ----------------------------------------------------------------
extern "C" void kernel_launch(void* const* d_in, const int* in_sizes, int n_in,
                              void* d_out, int out_size) {
    const float* x  = (const float*)d_in[0];       // [128, 8192]
    const int*   ei = (const int*)d_in[1];         // [2, E] int32
    const float* W  = (const float*)d_in[2];       // [128, 64]
    const float* b  = (const float*)d_in[3];       // [64]
    float* out = (float*)d_out;                    // [8192, 8192]
    const int E = in_sizes[1] / 2;

    k_count_h<<<1024 + N_NODES / 128, 256>>>(ei, E, x, W);   // 1
    k_zinit<<<(N_NODES * 16) / 256, 256>>>(b);               // 2
    k_edges<<<(E * 16) / 256, 256>>>(ei, E);                 // 3
    dim3 grid(N_NODES / 128, N_NODES / 128);
    k_gemm_sym<<<grid, 256>>>(out);                          // 4 <- ncu captures this
}

// round 11
// speedup vs baseline: 1.7975x; 1.4300x over previous
#include <cuda_runtime.h>
#include <cuda_bf16.h>
#include <cstdint>

#define N_NODES 8192
#define FIN 128
#define FOUT 64
#define EMAX 262144
#define SA 72            // smem row stride in bf16 elems (144 B): ldmatrix conflict-free

// Scratch (allocation-free rule: __device__ globals)
__device__ int   g_cnt[N_NODES];          // zero at entry; gemm dead-blocks re-zero it
__device__ float g_h[N_NODES * FOUT];
__device__ float g_z[N_NODES * FOUT];

// ---------------------------------------------------------------- launch 1: fused edge-count + h GEMM
__global__ void __launch_bounds__(256) k_count_h(const int* __restrict__ ei, int E,
                                                 const float* __restrict__ x,
                                                 const float* __restrict__ W) {
    int tid = threadIdx.x;
    if (blockIdx.x < 1024) {
        int e = blockIdx.x * 256 + tid;
        if (e < E) atomicAdd(&g_cnt[ei[E + e]], 1);
        return;
    }
    __shared__ float sW[FIN * FOUT];   // 32 KB
#pragma unroll
    for (int i = 0; i < 8; i++)
        ((float4*)sW)[tid + i * 256] = ((const float4*)W)[tid + i * 256];
    __syncthreads();

    int row = (blockIdx.x - 1024) * 128 + (tid & 127);
    int half = tid >> 7;
    const float4* sW4 = (const float4*)sW;

    unsigned long long acc2[16];
#pragma unroll
    for (int i = 0; i < 16; i++) acc2[i] = 0ull;

#pragma unroll 4
    for (int k = 0; k < FIN; k++) {
        float xv = __ldg(&x[k * N_NODES + row]);
        unsigned long long a2;
        asm("mov.b64 %0, {%1, %1};" : "=l"(a2) : "f"(xv));
        const float4* wrow = &sW4[k * 16 + half * 8];
#pragma unroll
        for (int q = 0; q < 8; q++) {
            float4 w = wrow[q];
            unsigned long long w0, w1;
            asm("mov.b64 %0, {%1, %2};" : "=l"(w0) : "f"(w.x), "f"(w.y));
            asm("mov.b64 %0, {%1, %2};" : "=l"(w1) : "f"(w.z), "f"(w.w));
            asm("fma.rn.f32x2 %0, %1, %2, %0;" : "+l"(acc2[q * 2])     : "l"(a2), "l"(w0));
            asm("fma.rn.f32x2 %0, %1, %2, %0;" : "+l"(acc2[q * 2 + 1]) : "l"(a2), "l"(w1));
        }
    }
    float* hp = &g_h[row * FOUT + half * 32];
#pragma unroll
    for (int q = 0; q < 8; q++) {
        float x0, y0, x1, y1;
        asm("mov.b64 {%0, %1}, %2;" : "=f"(x0), "=f"(y0) : "l"(acc2[q * 2]));
        asm("mov.b64 {%0, %1}, %2;" : "=f"(x1), "=f"(y1) : "l"(acc2[q * 2 + 1]));
        ((float4*)hp)[q] = make_float4(x0, y0, x1, y1);
    }
}

// ---------------------------------------------------------------- launch 2: z = h/deg + b
__global__ void k_zinit(const float* __restrict__ b) {
    int gid = blockIdx.x * blockDim.x + threadIdx.x;   // N * 16
    int n = gid >> 4, q = gid & 15;
    float inv = 1.0f / (float)(g_cnt[n] + 1);
    float4 h = *(const float4*)&g_h[n * FOUT + q * 4];
    float4 bb = __ldg(&((const float4*)b)[q]);
    float4 z;
    z.x = fmaf(h.x, inv, bb.x);
    z.y = fmaf(h.y, inv, bb.y);
    z.z = fmaf(h.z, inv, bb.z);
    z.w = fmaf(h.w, inv, bb.w);
    *(float4*)&g_z[n * FOUT + q * 4] = z;
}

// ---------------------------------------------------------------- launch 3: edge scatter, vector red
__global__ void k_edges(const int* __restrict__ ei, int E) {
    int gid = blockIdx.x * blockDim.x + threadIdx.x;   // E * 16
    int e = gid >> 4, q = gid & 15;
    if (e >= E) return;
    int s = __ldg(&ei[e]);
    int d = __ldg(&ei[E + e]);
    float degp = (float)((g_cnt[s] + 1) * (g_cnt[d] + 1));
    float c = rsqrtf(degp);
    float4 h = *(const float4*)&g_h[s * FOUT + q * 4];
    float* zp = &g_z[d * FOUT + q * 4];
    asm volatile("red.global.add.v4.f32 [%0], {%1, %2, %3, %4};"
                 :: "l"(zp), "f"(h.x * c), "f"(h.y * c), "f"(h.z * c), "f"(h.w * c)
                 : "memory");
}

// ---------------------------------------------------------------- launch 4: split-bf16 HMMA GEMM
__device__ __forceinline__ uint32_t smem_u32(const void* p) {
    uint32_t a;
    asm("{ .reg .u64 t; cvta.to.shared.u64 t, %1; cvt.u32.u64 %0, t; }" : "=r"(a) : "l"(p));
    return a;
}
__device__ __forceinline__ float sigmoid_tanh(float v) {
    float t;
    asm("tanh.approx.f32 %0, %1;" : "=f"(t) : "f"(0.5f * v));
    return fmaf(0.5f, t, 0.5f);
}
// pack 2 floats -> bf16x2 hi parts and residual lo parts
__device__ __forceinline__ void split2(float x, float y, uint32_t& hi, uint32_t& lo) {
    asm("cvt.rn.bf16x2.f32 %0, %1, %2;" : "=r"(hi) : "f"(y), "f"(x));   // hi16=y, lo16=x
    float hx = __uint_as_float(hi << 16);
    float hy = __uint_as_float(hi & 0xFFFF0000u);
    float rx = x - hx, ry = y - hy;
    asm("cvt.rn.bf16x2.f32 %0, %1, %2;" : "=r"(lo) : "f"(ry), "f"(rx));
}
#define LDSM4(r0, r1, r2, r3, addr) \
    asm volatile("ldmatrix.sync.aligned.m8n8.x4.shared.b16 {%0,%1,%2,%3}, [%4];" \
                 : "=r"(r0), "=r"(r1), "=r"(r2), "=r"(r3) : "r"(addr))
#define MMA16816(d, a, b0v, b1v) \
    asm volatile("mma.sync.aligned.m16n8k16.row.col.f32.bf16.bf16.f32 " \
                 "{%0,%1,%2,%3}, {%4,%5,%6,%7}, {%8,%9}, {%0,%1,%2,%3};" \
                 : "+f"((d)[0]), "+f"((d)[1]), "+f"((d)[2]), "+f"((d)[3]) \
                 : "r"((a)[0]), "r"((a)[1]), "r"((a)[2]), "r"((a)[3]), \
                   "r"(b0v), "r"(b1v))

#define GEMM_SMEM (4 * 128 * SA * 2)

__global__ void __launch_bounds__(256) k_gemm_mma(float* __restrict__ out) {
    const int bi = blockIdx.y, bj = blockIdx.x;
    if (bj < bi) {
        if (bj == 0 && bi >= 1 && bi <= 32)
            g_cnt[(bi - 1) * 256 + threadIdx.x] = 0;   // re-zero for next replay
        return;
    }
    const int i0 = bi * 128, j0 = bj * 128;
    extern __shared__ char dsm[];
    char* pAH = dsm;
    char* pAL = pAH + 128 * SA * 2;
    char* pBH = pAL + 128 * SA * 2;
    char* pBL = pBH + 128 * SA * 2;

    const int tid = threadIdx.x, lane = tid & 31, wid = tid >> 5;

    // ---- stage + split: 128 rows x 16 float4 reads per matrix ----
#pragma unroll
    for (int it = 0; it < 8; it++) {
        int idx = tid + it * 256;          // 0..2047
        int row = idx >> 4, q = idx & 15;
        uint32_t o = (uint32_t)(row * (SA * 2) + q * 8);   // byte offset, 8B aligned
        float4 v = *(const float4*)&g_z[(i0 + row) * FOUT + q * 4];
        uint32_t h0, l0, h1, l1;
        split2(v.x, v.y, h0, l0);
        split2(v.z, v.w, h1, l1);
        *(uint2*)(pAH + o) = make_uint2(h0, h1);
        *(uint2*)(pAL + o) = make_uint2(l0, l1);
        float4 u = *(const float4*)&g_z[(j0 + row) * FOUT + q * 4];
        split2(u.x, u.y, h0, l0);
        split2(u.z, u.w, h1, l1);
        *(uint2*)(pBH + o) = make_uint2(h0, h1);
        *(uint2*)(pBL + o) = make_uint2(l0, l1);
    }
    __syncthreads();

    const uint32_t aAH = smem_u32(pAH), aAL = smem_u32(pAL);
    const uint32_t aBH = smem_u32(pBH), aBL = smem_u32(pBL);

    const int wr = wid & 3, wc = wid >> 2;
    const int mbase = wr * 32, nbase = wc * 64;

    float d[2][8][4];
#pragma unroll
    for (int mi = 0; mi < 2; mi++)
#pragma unroll
        for (int j = 0; j < 8; j++)
#pragma unroll
            for (int t = 0; t < 4; t++) d[mi][j][t] = 0.f;

    const int arow = lane & 15, ahalf = lane >> 4;              // a-frag lane map
    const int brow = (lane & 7) + 8 * ((lane >> 3) & 1);        // b-frag lane map
    const int bhalf = lane >> 4;

#pragma unroll
    for (int ks = 0; ks < 4; ks++) {
        const int kb = ks * 16;
        uint32_t ah[2][4], al[2][4];
#pragma unroll
        for (int mi = 0; mi < 2; mi++) {
            uint32_t off = (uint32_t)(((mbase + mi * 16 + arow) * SA + kb + ahalf * 8) * 2);
            LDSM4(ah[mi][0], ah[mi][1], ah[mi][2], ah[mi][3], aAH + off);
            LDSM4(al[mi][0], al[mi][1], al[mi][2], al[mi][3], aAL + off);
        }
        uint32_t bh[8][2], bl[8][2];
#pragma unroll
        for (int jh = 0; jh < 4; jh++) {
            uint32_t off = (uint32_t)(((nbase + jh * 16 + brow) * SA + kb + bhalf * 8) * 2);
            uint32_t r0, r1, r2, r3;
            LDSM4(r0, r1, r2, r3, aBH + off);
            bh[jh * 2][0] = r0; bh[jh * 2][1] = r2;
            bh[jh * 2 + 1][0] = r1; bh[jh * 2 + 1][1] = r3;
            LDSM4(r0, r1, r2, r3, aBL + off);
            bl[jh * 2][0] = r0; bl[jh * 2][1] = r2;
            bl[jh * 2 + 1][0] = r1; bl[jh * 2 + 1][1] = r3;
        }
#pragma unroll
        for (int mi = 0; mi < 2; mi++)
#pragma unroll
            for (int j = 0; j < 8; j++) {
                MMA16816(d[mi][j], ah[mi], bh[j][0], bh[j][1]);
                MMA16816(d[mi][j], ah[mi], bl[j][0], bl[j][1]);
                MMA16816(d[mi][j], al[mi], bh[j][0], bh[j][1]);
            }
    }

    // ---- epilogue: sigmoid + direct & mirrored stores ----
    const int r0 = lane >> 2;            // 0..7
    const int cc = (lane & 3) * 2;
#pragma unroll
    for (int mi = 0; mi < 2; mi++) {
        const int gr0 = i0 + mbase + mi * 16 + r0;
#pragma unroll
        for (int j = 0; j < 8; j++) {
            const int gc = j0 + nbase + j * 8 + cc;
            float f0 = sigmoid_tanh(d[mi][j][0]);
            float f1 = sigmoid_tanh(d[mi][j][1]);
            float f2 = sigmoid_tanh(d[mi][j][2]);
            float f3 = sigmoid_tanh(d[mi][j][3]);
            *(float2*)&out[(size_t)gr0 * N_NODES + gc] = make_float2(f0, f1);
            *(float2*)&out[(size_t)(gr0 + 8) * N_NODES + gc] = make_float2(f2, f3);
            if (bi != bj) {
                out[(size_t)gc * N_NODES + gr0]           = f0;
                out[(size_t)(gc + 1) * N_NODES + gr0]     = f1;
                out[(size_t)gc * N_NODES + gr0 + 8]       = f2;
                out[(size_t)(gc + 1) * N_NODES + gr0 + 8] = f3;
            }
        }
    }
}

// ----------------------------------------------------------------
extern "C" void kernel_launch(void* const* d_in, const int* in_sizes, int n_in,
                              void* d_out, int out_size) {
    const float* x  = (const float*)d_in[0];       // [128, 8192]
    const int*   ei = (const int*)d_in[1];         // [2, E] int32
    const float* W  = (const float*)d_in[2];       // [128, 64]
    const float* b  = (const float*)d_in[3];       // [64]
    float* out = (float*)d_out;                    // [8192, 8192]
    const int E = in_sizes[1] / 2;

    cudaFuncSetAttribute(k_gemm_mma, cudaFuncAttributeMaxDynamicSharedMemorySize, GEMM_SMEM);

    k_count_h<<<1024 + N_NODES / 128, 256>>>(ei, E, x, W);   // 1
    k_zinit<<<(N_NODES * 16) / 256, 256>>>(b);               // 2
    k_edges<<<(E * 16) / 256, 256>>>(ei, E);                 // 3
    dim3 grid(N_NODES / 128, N_NODES / 128);
    k_gemm_mma<<<grid, 256, GEMM_SMEM>>>(out);               // 4 <- ncu captures this
}